// round 1
// baseline (speedup 1.0000x reference)
#include <cuda_runtime.h>
#include <math.h>

// Problem constants (fixed by setup_inputs)
#define NB    1024          // batch
#define CCH   128           // channels
#define HIM   64            // image H
#define WIM   64            // image W
#define NPIX  1024          // 32*32 grid pixels
#define KF    0.3f
#define OFF   0.35f         // (1-KF)/2

// ---------------- device scratch (no allocations allowed) ----------------
__device__ float g_h1[NB * 512];
__device__ float g_h2[NB * 256];
__device__ float g_h3[NB * 256];
__device__ float g_theta[NB * 36];
__device__ float g_vmm[NB * 4];   // vminx, vminy, vmaxx, vmaxy

// ---------------- per-n min/max over polargrid ----------------
__global__ __launch_bounds__(256) void minmax_kernel(const float* __restrict__ pg)
{
    const int n = blockIdx.x;
    const float2* p = (const float2*)pg + (size_t)n * NPIX;
    float mnx = 1e30f, mny = 1e30f, mxx = -1e30f, mxy = -1e30f;
    for (int i = threadIdx.x; i < NPIX; i += 256) {
        float2 v = p[i];
        mnx = fminf(mnx, v.x); mxx = fmaxf(mxx, v.x);
        mny = fminf(mny, v.y); mxy = fmaxf(mxy, v.y);
    }
#pragma unroll
    for (int o = 16; o > 0; o >>= 1) {
        mnx = fminf(mnx, __shfl_xor_sync(0xffffffffu, mnx, o));
        mny = fminf(mny, __shfl_xor_sync(0xffffffffu, mny, o));
        mxx = fmaxf(mxx, __shfl_xor_sync(0xffffffffu, mxx, o));
        mxy = fmaxf(mxy, __shfl_xor_sync(0xffffffffu, mxy, o));
    }
    __shared__ float red[8][4];
    int w = threadIdx.x >> 5, l = threadIdx.x & 31;
    if (l == 0) { red[w][0] = mnx; red[w][1] = mny; red[w][2] = mxx; red[w][3] = mxy; }
    __syncthreads();
    if (threadIdx.x == 0) {
        for (int i = 1; i < 8; i++) {
            mnx = fminf(mnx, red[i][0]); mny = fminf(mny, red[i][1]);
            mxx = fmaxf(mxx, red[i][2]); mxy = fmaxf(mxy, red[i][3]);
        }
        g_vmm[n * 4 + 0] = mnx; g_vmm[n * 4 + 1] = mny;
        g_vmm[n * 4 + 2] = mxx; g_vmm[n * 4 + 3] = mxy;
    }
}

// ---------------- fp32 tiled GEMM:  C = act(A @ W + bias) ----------------
// A: MxK row-major, W: KxN row-major. BM=BN=64, BK=16, 256 thr, 4x4/thread.
// ACT: 0 = relu, 1 = tanh
#define BM 64
#define BN 64
#define BK 16

template<int ACT>
__global__ __launch_bounds__(256) void gemm_act(
    const float* __restrict__ A, const float* __restrict__ W,
    const float* __restrict__ bias, float* __restrict__ C,
    int M, int K, int N)
{
    __shared__ float As[BK][BM];
    __shared__ float Bs[BK][BN];

    const int tid = threadIdx.x;
    const int bm = blockIdx.y * BM;
    const int bn = blockIdx.x * BN;
    const int tx = tid & 15;       // 16 col groups
    const int ty = tid >> 4;       // 16 row groups

    // A loader: thread -> row am (0..63), 4 consecutive k
    const int am = tid >> 2;
    const int ak = (tid & 3) * 4;
    // B loader: thread -> k row kr (0..15), 4 consecutive cols
    const int kr = tid >> 4;
    const int bc = (tid & 15) * 4;

    float acc[4][4] = {};

    for (int k0 = 0; k0 < K; k0 += BK) {
        // load A tile (M,K multiples of 64/16 here; always in-bounds)
        const float4 av = *(const float4*)(A + (size_t)(bm + am) * K + k0 + ak);
        As[ak + 0][am] = av.x; As[ak + 1][am] = av.y;
        As[ak + 2][am] = av.z; As[ak + 3][am] = av.w;
        // load W tile (guard N for the 36-wide last layer)
        const int col = bn + bc;
        const float* wptr = W + (size_t)(k0 + kr) * N + col;
        if (col + 3 < N) {
            const float4 wv = *(const float4*)wptr;  // 16B aligned: N*4 and col*4 are mult of 16
            Bs[kr][bc + 0] = wv.x; Bs[kr][bc + 1] = wv.y;
            Bs[kr][bc + 2] = wv.z; Bs[kr][bc + 3] = wv.w;
        } else {
#pragma unroll
            for (int j = 0; j < 4; j++)
                Bs[kr][bc + j] = (col + j < N) ? wptr[j] : 0.f;
        }
        __syncthreads();

#pragma unroll
        for (int k = 0; k < BK; k++) {
            const float4 a = *(const float4*)&As[k][ty * 4];
            const float4 b = *(const float4*)&Bs[k][tx * 4];
            const float ar[4] = { a.x, a.y, a.z, a.w };
            const float br[4] = { b.x, b.y, b.z, b.w };
#pragma unroll
            for (int i = 0; i < 4; i++)
#pragma unroll
                for (int j = 0; j < 4; j++)
                    acc[i][j] += ar[i] * br[j];
        }
        __syncthreads();
    }

#pragma unroll
    for (int i = 0; i < 4; i++) {
        const int row = bm + ty * 4 + i;
#pragma unroll
        for (int j = 0; j < 4; j++) {
            const int col = bn + tx * 4 + j;
            if (col < N) {
                float v = acc[i][j] + bias[col];
                v = (ACT == 0) ? fmaxf(v, 0.f) : tanhf(v);
                C[(size_t)row * N + col] = v;
            }
        }
    }
}

// ---------------- TPS warp + bilinear sampling ----------------
// One block per n. Phase 1: compute warped coords for 1024 pixels into smem.
// Phase 2: loop channels; stage 16KB image slice in smem; bilinear; coalesced store.
__global__ __launch_bounds__(256) void tps_sample_kernel(
    const float* __restrict__ polargrid,
    const float* __restrict__ imgs,
    const int*   __restrict__ imgIDs,
    float* __restrict__ out)
{
    __shared__ float s_tile[HIM * WIM];      // 16 KB
    __shared__ float s_wx[NPIX];             // 4 KB
    __shared__ float s_wy[NPIX];             // 4 KB
    __shared__ unsigned short s_xy[NPIX];    // 2 KB  (x0 | y0<<8)
    __shared__ float s_ctrl[16][2];
    __shared__ float s_w[16][2];
    __shared__ float s_a[3][2];

    const int n = blockIdx.x;
    const int tid = threadIdx.x;

    const float vminx = g_vmm[n * 4 + 0];
    const float vminy = g_vmm[n * 4 + 1];
    const float ptpx  = g_vmm[n * 4 + 2] - vminx;
    const float ptpy  = g_vmm[n * 4 + 3] - vminy;
    const float sKx = KF / ptpx;   // pg = (p - vmin) * (KF/ptp) + OFF
    const float sKy = KF / ptpy;

    // theta -> w (16x2, row 0 = -sum of the 15), a (3x2)
    if (tid < 2) {
        const int c = tid;
        const float* th = g_theta + (size_t)n * 36;
        float s = 0.f;
        for (int j = 0; j < 15; j++) {
            const float v = th[j * 2 + c];
            s += v;
            s_w[j + 1][c] = v;
        }
        s_w[0][c] = -s;
        s_a[0][c] = th[30 + c];
        s_a[1][c] = th[32 + c];
        s_a[2][c] = th[34 + c];
    }
    // control points from polargrid at (0,8,16,24)x(0,8,16,24)
    if (tid < 16) {
        const int ih = (tid >> 2) * 8, iw = (tid & 3) * 8;
        const float* p = polargrid + ((size_t)n * NPIX + ih * 32 + iw) * 2;
        s_ctrl[tid][0] = (p[0] - vminx) * sKx + OFF;
        s_ctrl[tid][1] = (p[1] - vminy) * sKy + OFF;
    }
    __syncthreads();

    // Phase 1: TPS-warped sample coordinates
    const float2* pgp = (const float2*)polargrid + (size_t)n * NPIX;
#pragma unroll
    for (int q = 0; q < 4; q++) {
        const int p = tid + q * 256;
        const float2 g = pgp[p];
        const float pgx = (g.x - vminx) * sKx + OFF;
        const float pgy = (g.y - vminy) * sKy + OFF;
        float zx = s_a[0][0] + pgx * s_a[1][0] + pgy * s_a[2][0];
        float zy = s_a[0][1] + pgx * s_a[1][1] + pgy * s_a[2][1];
#pragma unroll
        for (int j = 0; j < 16; j++) {
            const float dx = pgx - s_ctrl[j][0];
            const float dy = pgy - s_ctrl[j][1];
            const float d2 = dx * dx + dy * dy;
            const float u = d2 * logf(sqrtf(d2) + 1e-6f);
            zx += u * s_w[j][0];
            zy += u * s_w[j][1];
        }
        float twx = pgx + zx;
        float twy = pgy + zy;
        twx = (twx - OFF) * (ptpx / KF) + vminx;    // un-normalize
        twy = (twy - OFF) * (ptpy / KF) + vminy;
        // grid_sample border: ix = ((tw+1)*64 - 1)*0.5 = 32*tw + 31.5, clip [0,63]
        const float ix = fminf(fmaxf(32.f * twx + 31.5f, 0.f), 63.f);
        const float iy = fminf(fmaxf(32.f * twy + 31.5f, 0.f), 63.f);
        const float x0f = floorf(ix), y0f = floorf(iy);
        const int x0 = (int)x0f, y0 = (int)y0f;
        s_wx[p] = ix - x0f;
        s_wy[p] = iy - y0f;
        s_xy[p] = (unsigned short)(x0 | (y0 << 8));
    }
    __syncthreads();

    // Phase 2: per-channel bilinear from smem-staged 64x64 slice
    const int kimg = imgIDs[n];
    const float* img = imgs + (size_t)kimg * (CCH * HIM * WIM);
    float* outp = out + (size_t)n * (CCH * NPIX);

    for (int c = 0; c < CCH; c++) {
        const float4* src = (const float4*)(img + (size_t)c * (HIM * WIM));
        float4* dst = (float4*)s_tile;
#pragma unroll
        for (int q = 0; q < 4; q++)
            dst[tid + q * 256] = src[tid + q * 256];
        __syncthreads();

#pragma unroll
        for (int q = 0; q < 4; q++) {
            const int p = tid + q * 256;
            const unsigned xy = s_xy[p];
            const int x0 = xy & 255;
            const int y0 = xy >> 8;
            const int x1 = min(x0 + 1, WIM - 1);
            const int y1 = min(y0 + 1, HIM - 1);
            const float wx = s_wx[p], wy = s_wy[p];
            const float* r0 = s_tile + y0 * WIM;
            const float* r1 = s_tile + y1 * WIM;
            const float v00 = r0[x0], v01 = r0[x1];
            const float v10 = r1[x0], v11 = r1[x1];
            const float top = v00 + wx * (v01 - v00);
            const float bot = v10 + wx * (v11 - v10);
            outp[(size_t)c * NPIX + p] = top + wy * (bot - top);
        }
        __syncthreads();
    }
}

// ---------------- launch ----------------
extern "C" void kernel_launch(void* const* d_in, const int* in_sizes, int n_in,
                              void* d_out, int out_size)
{
    const float* polargrid = (const float*)d_in[0];
    const float* xt        = (const float*)d_in[1];
    const float* imgs      = (const float*)d_in[2];
    const int*   imgIDs    = (const int*)  d_in[3];
    const float* W1 = (const float*)d_in[4];
    const float* b1 = (const float*)d_in[5];
    const float* W2 = (const float*)d_in[6];
    const float* b2 = (const float*)d_in[7];
    const float* W3 = (const float*)d_in[8];
    const float* b3 = (const float*)d_in[9];
    const float* W4 = (const float*)d_in[10];
    const float* b4 = (const float*)d_in[11];
    float* out = (float*)d_out;

    float *h1, *h2, *h3, *theta;
    cudaGetSymbolAddress((void**)&h1, g_h1);
    cudaGetSymbolAddress((void**)&h2, g_h2);
    cudaGetSymbolAddress((void**)&h3, g_h3);
    cudaGetSymbolAddress((void**)&theta, g_theta);

    minmax_kernel<<<NB, 256>>>(polargrid);

    gemm_act<0><<<dim3(512 / BN, NB / BM), 256>>>(xt, W1, b1, h1, NB, 3200, 512);
    gemm_act<0><<<dim3(256 / BN, NB / BM), 256>>>(h1, W2, b2, h2, NB, 512, 256);
    gemm_act<0><<<dim3(256 / BN, NB / BM), 256>>>(h2, W3, b3, h3, NB, 256, 256);
    gemm_act<1><<<dim3(1,        NB / BM), 256>>>(h3, W4, b4, theta, NB, 256, 36);

    tps_sample_kernel<<<NB, 256>>>(polargrid, imgs, imgIDs, out);
}

// round 2
// speedup vs baseline: 1.4624x; 1.4624x over previous
#include <cuda_runtime.h>
#include <math.h>

// Problem constants (fixed by setup_inputs)
#define NB    1024          // batch
#define CCH   128           // channels
#define HIM   64            // image H
#define WIM   64            // image W
#define NPIX  1024          // 32*32 grid pixels
#define KF    0.3f
#define OFF   0.35f         // (1-KF)/2
#define G     8             // batch items per sampling group
#define NGROUPS 136         // max groups: 128 + 8 (per-bucket padding)

typedef unsigned long long u64;

// ---------------- device scratch (no allocations allowed) ----------------
__device__ float g_h1[NB * 512];
__device__ float g_h2[NB * 256];
__device__ float g_h3[NB * 256];
__device__ float g_theta[NB * 36];
__device__ float g_vmm[NB * 4];          // vminx, vminy, vmaxx, vmaxy
__device__ uint2 g_coords[NB * NPIX];    // packed warped coords
__device__ int   g_list[NGROUPS * G];    // n indices per group (-1 = pad)
__device__ int   g_gimg[NGROUPS];        // image id per group

// ---------------- per-n min/max over polargrid ----------------
__global__ __launch_bounds__(256) void minmax_kernel(const float* __restrict__ pg)
{
    const int n = blockIdx.x;
    const float2* p = (const float2*)pg + (size_t)n * NPIX;
    float mnx = 1e30f, mny = 1e30f, mxx = -1e30f, mxy = -1e30f;
    for (int i = threadIdx.x; i < NPIX; i += 256) {
        float2 v = p[i];
        mnx = fminf(mnx, v.x); mxx = fmaxf(mxx, v.x);
        mny = fminf(mny, v.y); mxy = fmaxf(mxy, v.y);
    }
#pragma unroll
    for (int o = 16; o > 0; o >>= 1) {
        mnx = fminf(mnx, __shfl_xor_sync(0xffffffffu, mnx, o));
        mny = fminf(mny, __shfl_xor_sync(0xffffffffu, mny, o));
        mxx = fmaxf(mxx, __shfl_xor_sync(0xffffffffu, mxx, o));
        mxy = fmaxf(mxy, __shfl_xor_sync(0xffffffffu, mxy, o));
    }
    __shared__ float red[8][4];
    int w = threadIdx.x >> 5, l = threadIdx.x & 31;
    if (l == 0) { red[w][0] = mnx; red[w][1] = mny; red[w][2] = mxx; red[w][3] = mxy; }
    __syncthreads();
    if (threadIdx.x == 0) {
        for (int i = 1; i < 8; i++) {
            mnx = fminf(mnx, red[i][0]); mny = fminf(mny, red[i][1]);
            mxx = fmaxf(mxx, red[i][2]); mxy = fmaxf(mxy, red[i][3]);
        }
        g_vmm[n * 4 + 0] = mnx; g_vmm[n * 4 + 1] = mny;
        g_vmm[n * 4 + 2] = mxx; g_vmm[n * 4 + 3] = mxy;
    }
}

// ---------------- group n's by image id (counting sort, 1 block) ----------
__global__ __launch_bounds__(256) void prep_groups(const int* __restrict__ ids)
{
    __shared__ int cnt[8], base[8], off[8];
    const int t = threadIdx.x;
    if (t < 8) { cnt[t] = 0; off[t] = 0; }
    __syncthreads();
    for (int i = t; i < NB; i += 256) atomicAdd(&cnt[ids[i]], 1);
    for (int i = t; i < NGROUPS * G; i += 256) g_list[i] = -1;
    for (int i = t; i < NGROUPS; i += 256) g_gimg[i] = 0;
    __syncthreads();
    if (t == 0) {
        int p = 0;
        for (int k = 0; k < 8; k++) {
            base[k] = p;
            const int ng = (cnt[k] + G - 1) / G;
            for (int j = 0; j < ng; j++) g_gimg[p / G + j] = k;
            p += ng * G;
        }
    }
    __syncthreads();
    for (int i = t; i < NB; i += 256) {
        const int k = ids[i];
        const int r = atomicAdd(&off[k], 1);
        g_list[base[k] + r] = i;
    }
}

// ---------------- fp32 tiled GEMM with packed f32x2 FMA -------------------
// C = act(A @ W + bias). A: MxK row-major, W: KxN row-major.
// BM=BN=64, BK=16, 256 thr, 4x4 per thread (as 4x2 f32x2 pairs).
#define BM 64
#define BN 64
#define BK 16

#define FFMA2(ACCV, AV, BV) \
    asm("fma.rn.f32x2 %0, %1, %2, %0;" : "+l"(ACCV) : "l"(AV), "l"(BV))

template<int ACT>  // 0 = relu, 1 = tanh
__global__ __launch_bounds__(256) void gemm_act(
    const float* __restrict__ A, const float* __restrict__ W,
    const float* __restrict__ bias, float* __restrict__ C,
    int M, int K, int N)
{
    __shared__ float As[BK][BM];
    __shared__ float Bs[BK][BN];

    const int tid = threadIdx.x;
    const int bm = blockIdx.y * BM;
    const int bn = blockIdx.x * BN;
    const int tx = tid & 15;
    const int ty = tid >> 4;

    const int am = tid >> 2;
    const int ak = (tid & 3) * 4;
    const int kr = tid >> 4;
    const int bc = (tid & 15) * 4;

    u64 acc[4][2] = {};

    for (int k0 = 0; k0 < K; k0 += BK) {
        const float4 av = *(const float4*)(A + (size_t)(bm + am) * K + k0 + ak);
        As[ak + 0][am] = av.x; As[ak + 1][am] = av.y;
        As[ak + 2][am] = av.z; As[ak + 3][am] = av.w;
        const int col = bn + bc;
        const float* wptr = W + (size_t)(k0 + kr) * N + col;
        if (col + 3 < N) {
            const float4 wv = *(const float4*)wptr;
            Bs[kr][bc + 0] = wv.x; Bs[kr][bc + 1] = wv.y;
            Bs[kr][bc + 2] = wv.z; Bs[kr][bc + 3] = wv.w;
        } else {
#pragma unroll
            for (int j = 0; j < 4; j++)
                Bs[kr][bc + j] = (col + j < N) ? wptr[j] : 0.f;
        }
        __syncthreads();

#pragma unroll
        for (int k = 0; k < BK; k++) {
            const float4 a = *(const float4*)&As[k][ty * 4];
            const u64* bp = (const u64*)&Bs[k][tx * 4];
            const u64 b0 = bp[0];
            const u64 b1 = bp[1];
            const float ar[4] = { a.x, a.y, a.z, a.w };
#pragma unroll
            for (int i = 0; i < 4; i++) {
                u64 aa;
                asm("mov.b64 %0, {%1, %1};" : "=l"(aa) : "f"(ar[i]));
                FFMA2(acc[i][0], aa, b0);
                FFMA2(acc[i][1], aa, b1);
            }
        }
        __syncthreads();
    }

#pragma unroll
    for (int i = 0; i < 4; i++) {
        const int row = bm + ty * 4 + i;
#pragma unroll
        for (int jp = 0; jp < 2; jp++) {
            float lo, hi;
            asm("mov.b64 {%0, %1}, %2;" : "=f"(lo), "=f"(hi) : "l"(acc[i][jp]));
            const int col = bn + tx * 4 + jp * 2;
            if (col < N) {
                float v = lo + bias[col];
                C[(size_t)row * N + col] = (ACT == 0) ? fmaxf(v, 0.f) : tanhf(v);
            }
            if (col + 1 < N) {
                float v = hi + bias[col + 1];
                C[(size_t)row * N + col + 1] = (ACT == 0) ? fmaxf(v, 0.f) : tanhf(v);
            }
        }
    }
}

// ---------------- TPS warp -> packed sample coords -------------------------
__global__ __launch_bounds__(256) void coords_kernel(const float* __restrict__ polargrid)
{
    __shared__ float s_ctrl[16][2];
    __shared__ float s_w[16][2];
    __shared__ float s_a[3][2];

    const int n = blockIdx.x;
    const int tid = threadIdx.x;

    const float vminx = g_vmm[n * 4 + 0];
    const float vminy = g_vmm[n * 4 + 1];
    const float ptpx  = g_vmm[n * 4 + 2] - vminx;
    const float ptpy  = g_vmm[n * 4 + 3] - vminy;
    const float sKx = KF / ptpx;
    const float sKy = KF / ptpy;

    if (tid < 2) {
        const int c = tid;
        const float* th = g_theta + (size_t)n * 36;
        float s = 0.f;
        for (int j = 0; j < 15; j++) {
            const float v = th[j * 2 + c];
            s += v;
            s_w[j + 1][c] = v;
        }
        s_w[0][c] = -s;
        s_a[0][c] = th[30 + c];
        s_a[1][c] = th[32 + c];
        s_a[2][c] = th[34 + c];
    }
    if (tid < 16) {
        const int ih = (tid >> 2) * 8, iw = (tid & 3) * 8;
        const float* p = polargrid + ((size_t)n * NPIX + ih * 32 + iw) * 2;
        s_ctrl[tid][0] = (p[0] - vminx) * sKx + OFF;
        s_ctrl[tid][1] = (p[1] - vminy) * sKy + OFF;
    }
    __syncthreads();

    const float2* pgp = (const float2*)polargrid + (size_t)n * NPIX;
#pragma unroll
    for (int q = 0; q < 4; q++) {
        const int p = tid + q * 256;
        const float2 g = pgp[p];
        const float pgx = (g.x - vminx) * sKx + OFF;
        const float pgy = (g.y - vminy) * sKy + OFF;
        float zx = s_a[0][0] + pgx * s_a[1][0] + pgy * s_a[2][0];
        float zy = s_a[0][1] + pgx * s_a[1][1] + pgy * s_a[2][1];
#pragma unroll
        for (int j = 0; j < 16; j++) {
            const float dx = pgx - s_ctrl[j][0];
            const float dy = pgy - s_ctrl[j][1];
            const float d2 = dx * dx + dy * dy;
            const float u = d2 * logf(sqrtf(d2) + 1e-6f);
            zx += u * s_w[j][0];
            zy += u * s_w[j][1];
        }
        float twx = pgx + zx;
        float twy = pgy + zy;
        twx = (twx - OFF) * (ptpx / KF) + vminx;
        twy = (twy - OFF) * (ptpy / KF) + vminy;
        const float ix = fminf(fmaxf(32.f * twx + 31.5f, 0.f), 63.f);
        const float iy = fminf(fmaxf(32.f * twy + 31.5f, 0.f), 63.f);
        const float x0f = floorf(ix), y0f = floorf(iy);
        const int x0 = (int)x0f, y0 = (int)y0f;
        const float wx = ix - x0f, wy = iy - y0f;
        const unsigned dxf = (x0 < WIM - 1) ? 1u : 0u;
        const unsigned dyf = (y0 < HIM - 1) ? 1u : 0u;
        const unsigned w0 = (unsigned)(y0 * WIM + x0) | (dxf << 12) | (dyf << 13);
        const unsigned wxq = (unsigned)(wx * 65535.f + 0.5f);
        const unsigned wyq = (unsigned)(wy * 65535.f + 0.5f);
        g_coords[(size_t)n * NPIX + p] = make_uint2(w0, wxq | (wyq << 16));
    }
}

// ---------------- grouped bilinear sampling --------------------------------
// Block = (group of G n's sharing one image) x (half of the channels).
// Coords live in registers; channel tiles double-buffered via cp.async.
#define CP16(dst, src) \
    asm volatile("cp.async.ca.shared.global [%0], [%1], 16;" :: "r"(dst), "l"(src))

__global__ __launch_bounds__(256, 2) void sample_kernel(
    const float* __restrict__ imgs, float* __restrict__ out)
{
    __shared__ float tile[2][HIM * WIM];   // 2 x 16KB

    const int grp  = blockIdx.x >> 1;
    const int half = blockIdx.x & 1;
    const int tid  = threadIdx.x;

    __shared__ int s_n[G];
    __shared__ int s_img;
    if (tid < G) s_n[tid] = g_list[grp * G + tid];
    if (tid == 0) s_img = g_gimg[grp];
    __syncthreads();

    if (s_n[0] < 0) return;   // fully padded / unused group

    int n_r[G];
#pragma unroll
    for (int i = 0; i < G; i++) n_r[i] = s_n[i];

    // Load packed coords for this block's 8192 pixels into registers.
    unsigned cw0[32], cw1[32];
#pragma unroll
    for (int q = 0; q < 32; q++) {
        const int n = n_r[q >> 2];
        if (n >= 0) {
            const uint2 c = g_coords[(size_t)n * NPIX + ((q & 3) << 8) + tid];
            cw0[q] = c.x; cw1[q] = c.y;
        } else { cw0[q] = 0; cw1[q] = 0; }
    }

    const int cbeg = half * (CCH / 2);
    const float* img = imgs + (size_t)s_img * (CCH * HIM * WIM);
    const unsigned sbase = (unsigned)__cvta_generic_to_shared(&tile[0][0]);

    // stage first channel
    {
        const char* src = (const char*)(img + (size_t)cbeg * (HIM * WIM));
#pragma unroll
        for (int j = 0; j < 4; j++)
            CP16(sbase + (tid + 256 * j) * 16, src + (tid + 256 * j) * 16);
        asm volatile("cp.async.commit_group;");
    }

    for (int ci = 0; ci < CCH / 2; ci++) {
        if (ci < CCH / 2 - 1) {
            const unsigned db = sbase + ((ci + 1) & 1) * (HIM * WIM * 4);
            const char* src = (const char*)(img + (size_t)(cbeg + ci + 1) * (HIM * WIM));
#pragma unroll
            for (int j = 0; j < 4; j++)
                CP16(db + (tid + 256 * j) * 16, src + (tid + 256 * j) * 16);
            asm volatile("cp.async.commit_group;");
            asm volatile("cp.async.wait_group 1;");
        } else {
            asm volatile("cp.async.wait_group 0;");
        }
        __syncthreads();

        const float* tl = tile[ci & 1];
        const int c = cbeg + ci;
#pragma unroll
        for (int q = 0; q < 32; q++) {
            const unsigned a = cw0[q], b = cw1[q];
            const int o  = a & 0xFFF;
            const int dx = (a >> 12) & 1;
            const int dy = ((a >> 13) & 1) << 6;
            const float wx = (float)(b & 0xFFFF) * (1.f / 65535.f);
            const float wy = (float)(b >> 16)    * (1.f / 65535.f);
            const float v00 = tl[o];
            const float v01 = tl[o + dx];
            const float v10 = tl[o + dy];
            const float v11 = tl[o + dy + dx];
            const float top = v00 + wx * (v01 - v00);
            const float bot = v10 + wx * (v11 - v10);
            const float r   = top + wy * (bot - top);
            const int n = n_r[q >> 2];
            if (n >= 0)
                out[((size_t)(unsigned)n << 17) + ((size_t)c << 10) + ((q & 3) << 8) + tid] = r;
        }
        __syncthreads();
    }
}

// ---------------- launch ----------------
extern "C" void kernel_launch(void* const* d_in, const int* in_sizes, int n_in,
                              void* d_out, int out_size)
{
    const float* polargrid = (const float*)d_in[0];
    const float* xt        = (const float*)d_in[1];
    const float* imgs      = (const float*)d_in[2];
    const int*   imgIDs    = (const int*)  d_in[3];
    const float* W1 = (const float*)d_in[4];
    const float* b1 = (const float*)d_in[5];
    const float* W2 = (const float*)d_in[6];
    const float* b2 = (const float*)d_in[7];
    const float* W3 = (const float*)d_in[8];
    const float* b3 = (const float*)d_in[9];
    const float* W4 = (const float*)d_in[10];
    const float* b4 = (const float*)d_in[11];
    float* out = (float*)d_out;

    float *h1, *h2, *h3, *theta;
    cudaGetSymbolAddress((void**)&h1, g_h1);
    cudaGetSymbolAddress((void**)&h2, g_h2);
    cudaGetSymbolAddress((void**)&h3, g_h3);
    cudaGetSymbolAddress((void**)&theta, g_theta);

    minmax_kernel<<<NB, 256>>>(polargrid);
    prep_groups<<<1, 256>>>(imgIDs);

    gemm_act<0><<<dim3(512 / BN, NB / BM), 256>>>(xt, W1, b1, h1, NB, 3200, 512);
    gemm_act<0><<<dim3(256 / BN, NB / BM), 256>>>(h1, W2, b2, h2, NB, 512, 256);
    gemm_act<0><<<dim3(256 / BN, NB / BM), 256>>>(h2, W3, b3, h3, NB, 256, 256);
    gemm_act<1><<<dim3(1,        NB / BM), 256>>>(h3, W4, b4, theta, NB, 256, 36);

    coords_kernel<<<NB, 256>>>(polargrid);
    sample_kernel<<<NGROUPS * 2, 256>>>(imgs, out);
}